// round 1
// baseline (speedup 1.0000x reference)
#include <cuda_runtime.h>
#include <cuda_bf16.h>
#include <cstdint>

// Problem constants
#define Bb 8
#define Ss 2048
#define Hh 3584
#define Ee 8
#define Rr 16
#define Kk 2
#define Jj 32            // K*R combined rank
#define SCALING 2.0f     // lora_alpha / lora_r = 32/16

// Scratch (static device globals — no allocation)
__device__ float2 g_Acd[(size_t)Bb * Hh * Jj];     // [b][h][j], value duplicated (v,v); w*scaling folded in
__device__ float  g_Bc [(size_t)Bb * Jj * Hh];     // [b][j][h]
__device__ float2 g_lowdup[(size_t)Bb * Ss * Jj];  // [token][j], duplicated (v,v)

union U2 { unsigned long long u; float2 f; };

__device__ __forceinline__ unsigned long long fma2(unsigned long long a,
                                                   unsigned long long b,
                                                   unsigned long long c) {
    unsigned long long d;
    asm("fma.rn.f32x2 %0, %1, %2, %3;" : "=l"(d) : "l"(a), "l"(b), "l"(c));
    return d;
}

// ---------------------------------------------------------------------------
// prep: build Ac (dup, [b][h][j]) and Bc ([b][j][h]) from routed experts.
// grid (Bb, Jj), 256 threads.
// ---------------------------------------------------------------------------
__global__ void prep_kernel(const float* __restrict__ A,   // [E,R,H]
                            const float* __restrict__ Bm,  // [E,H,R]
                            const float* __restrict__ w,   // [B,K]
                            const int*   __restrict__ idx) // [B,K]
{
    int b = blockIdx.x;
    int j = blockIdx.y;
    int k = j >> 4;       // j / R
    int r = j & 15;       // j % R
    int e = idx[b * Kk + k];
    float sc = w[b * Kk + k] * SCALING;
    const float* arow = A + ((size_t)e * Rr + r) * Hh;
    const float* bcol = Bm + (size_t)e * Hh * Rr + r;
    for (int h = threadIdx.x; h < Hh; h += blockDim.x) {
        float v = sc * arow[h];
        g_Acd[((size_t)b * Hh + h) * Jj + j] = make_float2(v, v);
        g_Bc [((size_t)b * Jj + j) * Hh + h] = bcol[(size_t)h * Rr];
    }
}

// ---------------------------------------------------------------------------
// low: low[tok][j] = sum_h x[tok][h] * Ac[b][j][h]   (w*scaling already in Ac)
// grid 256 (64-token tiles), 128 threads.
// Thread = 4 j (jg) x 4 tokens (sg), tokens packed in pairs as f32x2.
// ---------------------------------------------------------------------------
#define K1_TOK 64
#define KC 32

__global__ void __launch_bounds__(128) low_kernel(const float* __restrict__ x)
{
    __shared__ __align__(16) float  xs[KC][68];      // [k][tok], padded
    __shared__ __align__(16) float2 as_d[KC][Jj];    // [k][j], duplicated values

    int tid = threadIdx.x;
    int jg = tid & 7;          // 8 j-groups of 4
    int sg = tid >> 3;         // 16 token-groups of 4
    int tokbase = blockIdx.x * K1_TOK;
    int b = tokbase / Ss;

    unsigned long long acc[8];
#pragma unroll
    for (int i = 0; i < 8; i++) acc[i] = 0ULL;

    const float2* acsrc = g_Acd + (size_t)b * Hh * Jj;

    for (int k0 = 0; k0 < Hh; k0 += KC) {
        __syncthreads();
        // x tile: 64 tok x 32 k, transposed into [k][tok]
#pragma unroll
        for (int i = 0; i < 4; i++) {
            int f4 = tid + 128 * i;
            int tok = f4 >> 3, kq = f4 & 7;
            float4 v = *(const float4*)&x[(size_t)(tokbase + tok) * Hh + k0 + kq * 4];
            xs[kq * 4 + 0][tok] = v.x;
            xs[kq * 4 + 1][tok] = v.y;
            xs[kq * 4 + 2][tok] = v.z;
            xs[kq * 4 + 3][tok] = v.w;
        }
        // A chunk: 32 k x 32 j float2 (already duplicated + in [h][j] layout)
#pragma unroll
        for (int i = 0; i < 4; i++) {
            int f4 = tid + 128 * i;
            int kk = f4 >> 4, jq = f4 & 15;
            *(float4*)&as_d[kk][jq * 2] =
                *(const float4*)&acsrc[(size_t)(k0 + kk) * Jj + jq * 2];
        }
        __syncthreads();
#pragma unroll
        for (int kk = 0; kk < KC; kk++) {
            ulonglong2 xv  = *(ulonglong2*)&xs[kk][sg * 4];        // tok pairs (0,1),(2,3)
            ulonglong2 a01 = *(ulonglong2*)&as_d[kk][jg * 4];      // j0,j1 dup
            ulonglong2 a23 = *(ulonglong2*)&as_d[kk][jg * 4 + 2];  // j2,j3 dup
            acc[0] = fma2(xv.x, a01.x, acc[0]);
            acc[1] = fma2(xv.y, a01.x, acc[1]);
            acc[2] = fma2(xv.x, a01.y, acc[2]);
            acc[3] = fma2(xv.y, a01.y, acc[3]);
            acc[4] = fma2(xv.x, a23.x, acc[4]);
            acc[5] = fma2(xv.y, a23.x, acc[5]);
            acc[6] = fma2(xv.x, a23.y, acc[6]);
            acc[7] = fma2(xv.y, a23.y, acc[7]);
        }
    }

    // Write duplicated low values
#pragma unroll
    for (int c = 0; c < 4; c++) {
#pragma unroll
        for (int tp = 0; tp < 2; tp++) {
            U2 u; u.u = acc[c * 2 + tp];
            int j = jg * 4 + c;
            int t0 = tokbase + sg * 4 + tp * 2;
            g_lowdup[(size_t)t0 * Jj + j]       = make_float2(u.f.x, u.f.x);
            g_lowdup[(size_t)(t0 + 1) * Jj + j] = make_float2(u.f.y, u.f.y);
        }
    }
}

// ---------------------------------------------------------------------------
// out: out[tok][h] = base[tok][h] + sum_j low[tok][j] * Bc[b][j][h]
// grid (512 token-tiles of 32, 14 h-tiles of 256), 128 threads.
// Thread = 4 h (2 f32x2 accs) x 8 tokens per pass, 2 passes.
// ---------------------------------------------------------------------------
#define HT 256
#define TT 32

__global__ void __launch_bounds__(128) out_kernel(const float* __restrict__ base,
                                                  float* __restrict__ out)
{
    __shared__ __align__(16) float  sB[Jj][HT];      // 32 KB
    __shared__ __align__(16) float2 sLowT[Jj][36];   // [j][tok], padded

    int tid = threadIdx.x;
    int h0 = blockIdx.y * HT;
    int tok0 = blockIdx.x * TT;
    int b = tok0 >> 11;  // / 2048

    const float* bc = g_Bc + (size_t)b * Jj * Hh + h0;
#pragma unroll
    for (int i = 0; i < 16; i++) {           // 32*256 floats = 2048 float4
        int f4 = tid + 128 * i;
        int j = f4 >> 6;
        int hq = f4 & 63;
        *(float4*)&sB[j][hq * 4] = *(const float4*)&bc[(size_t)j * Hh + hq * 4];
    }
#pragma unroll
    for (int i = 0; i < 8; i++) {            // 32 tok x 32 j float2
        int iv = tid + 128 * i;
        int j = iv & 31;                     // coalesced global read (j fast)
        int t = iv >> 5;
        sLowT[j][t] = g_lowdup[(size_t)(tok0 + t) * Jj + j];
    }
    __syncthreads();

    int g = tid >> 6;        // token half (16 tokens each)
    int hq = tid & 63;       // h offset = hq*4

#pragma unroll
    for (int p = 0; p < 2; p++) {
        int tl = g * 16 + p * 8;             // 8 tokens this pass
        unsigned long long acc[8][2];
#pragma unroll
        for (int t = 0; t < 8; t++) { acc[t][0] = 0ULL; acc[t][1] = 0ULL; }

#pragma unroll
        for (int j = 0; j < Jj; j++) {
            ulonglong2 bv = *(ulonglong2*)&sB[j][hq * 4];       // (h0h1),(h2h3)
            ulonglong2 l0 = *(ulonglong2*)&sLowT[j][tl];
            ulonglong2 l1 = *(ulonglong2*)&sLowT[j][tl + 2];
            ulonglong2 l2 = *(ulonglong2*)&sLowT[j][tl + 4];
            ulonglong2 l3 = *(ulonglong2*)&sLowT[j][tl + 6];
            acc[0][0] = fma2(bv.x, l0.x, acc[0][0]); acc[0][1] = fma2(bv.y, l0.x, acc[0][1]);
            acc[1][0] = fma2(bv.x, l0.y, acc[1][0]); acc[1][1] = fma2(bv.y, l0.y, acc[1][1]);
            acc[2][0] = fma2(bv.x, l1.x, acc[2][0]); acc[2][1] = fma2(bv.y, l1.x, acc[2][1]);
            acc[3][0] = fma2(bv.x, l1.y, acc[3][0]); acc[3][1] = fma2(bv.y, l1.y, acc[3][1]);
            acc[4][0] = fma2(bv.x, l2.x, acc[4][0]); acc[4][1] = fma2(bv.y, l2.x, acc[4][1]);
            acc[5][0] = fma2(bv.x, l2.y, acc[5][0]); acc[5][1] = fma2(bv.y, l2.y, acc[5][1]);
            acc[6][0] = fma2(bv.x, l3.x, acc[6][0]); acc[6][1] = fma2(bv.y, l3.x, acc[6][1]);
            acc[7][0] = fma2(bv.x, l3.y, acc[7][0]); acc[7][1] = fma2(bv.y, l3.y, acc[7][1]);
        }

#pragma unroll
        for (int t = 0; t < 8; t++) {
            size_t gi = (size_t)(tok0 + tl + t) * Hh + h0 + hq * 4;
            float4 bs = *(const float4*)&base[gi];
            U2 a0, a1; a0.u = acc[t][0]; a1.u = acc[t][1];
            float4 o = make_float4(bs.x + a0.f.x, bs.y + a0.f.y,
                                   bs.z + a1.f.x, bs.w + a1.f.y);
            *(float4*)&out[gi] = o;
        }
    }
}

// ---------------------------------------------------------------------------
extern "C" void kernel_launch(void* const* d_in, const int* in_sizes, int n_in,
                              void* d_out, int out_size)
{
    const float* x    = (const float*)d_in[0];
    const float* base = (const float*)d_in[1];
    const float* lA   = (const float*)d_in[2];
    const float* lB   = (const float*)d_in[3];
    const float* w    = (const float*)d_in[4];
    const int*   idx  = (const int*)  d_in[5];
    float* out = (float*)d_out;

    prep_kernel<<<dim3(Bb, Jj), 256>>>(lA, lB, w, idx);
    low_kernel<<<(Bb * Ss) / K1_TOK, 128>>>(x);
    out_kernel<<<dim3((Bb * Ss) / TT, Hh / HT), 128>>>(base, out);
}

// round 4
// speedup vs baseline: 1.4049x; 1.4049x over previous
#include <cuda_runtime.h>
#include <cuda_bf16.h>
#include <cstdint>

#define Bb 8
#define Ss 2048
#define Hh 3584
#define Ee 8
#define Rr 16
#define Kk 2
#define Jj 32
#define SCALING 2.0f

#define NSPLIT 4
#define HSPLIT (Hh / NSPLIT)     // 896
#define KC 32
#define NCHUNK (HSPLIT / KC)     // 28
#define NTOK (Bb * Ss)           // 16384

// Scratch (static device globals — no allocation). All 16B-aligned: accessed
// through float4/ulonglong2 casts.
__device__ __align__(16) float2 g_Acd[(size_t)Bb * Hh * Jj];        // [b][h][j], dup (v,v), w*scaling folded
__device__ __align__(16) float  g_Bc [(size_t)Bb * Jj * Hh];        // [b][j][h]
__device__ __align__(16) float  g_lowp[(size_t)NSPLIT * NTOK * Jj]; // partial lows [split][tok][j]
__device__ __align__(16) float2 g_lowdup[(size_t)NTOK * Jj];        // [tok][j], dup (v,v)

union U2 { unsigned long long u; float2 f; };

__device__ __forceinline__ unsigned long long fma2(unsigned long long a,
                                                   unsigned long long b,
                                                   unsigned long long c) {
    unsigned long long d;
    asm("fma.rn.f32x2 %0, %1, %2, %3;" : "=l"(d) : "l"(a), "l"(b), "l"(c));
    return d;
}

// ---------------------------------------------------------------------------
// prep: Acd [b][h][j] dup f2 (coalesced j-fast writes) and Bc [b][j][h].
// grid (Bb, Hh/256), 256 threads.
// ---------------------------------------------------------------------------
__global__ void __launch_bounds__(256) prep_kernel(const float* __restrict__ A,
                                                   const float* __restrict__ Bm,
                                                   const float* __restrict__ w,
                                                   const int*   __restrict__ idx)
{
    __shared__ int   es[Jj];
    __shared__ float scs[Jj];
    int b = blockIdx.x;
    int hb = blockIdx.y * 256;
    int tid = threadIdx.x;
    if (tid < Jj) {
        int k = tid >> 4;
        es[tid]  = idx[b * Kk + k];
        scs[tid] = w[b * Kk + k] * SCALING;
    }
    __syncthreads();

    // Acd: j fast -> coalesced 256B stores
    for (int t = tid; t < 256 * Jj; t += 256) {
        int h = hb + (t >> 5);
        int j = t & 31;
        int r = j & 15;
        float v = A[((size_t)(es[j] * Rr + r)) * Hh + h] * scs[j];
        g_Acd[((size_t)b * Hh + h) * Jj + j] = make_float2(v, v);
    }
    // Bc: h fast -> coalesced stores
    for (int t = tid; t < 256 * Jj; t += 256) {
        int j = t >> 8;
        int h = hb + (t & 255);
        int r = j & 15;
        g_Bc[((size_t)b * Jj + j) * Hh + h] =
            Bm[((size_t)es[j] * Hh + h) * Rr + r];
    }
}

// ---------------------------------------------------------------------------
// low: partial low over a k-split. grid (256 tok-tiles, NSPLIT), 128 threads.
// Register-prefetch pipeline hides global latency behind FMA compute.
// Thread = 4 j x 4 tokens (token pairs as f32x2).
// ---------------------------------------------------------------------------
__global__ void __launch_bounds__(128) low_kernel(const float* __restrict__ x)
{
    __shared__ __align__(16) float  xs[KC][68];     // [k][tok]; 68*4=272B row stride (16B-aligned)
    __shared__ __align__(16) float2 as_d[KC][Jj];   // [k][j] dup, contiguous chunk image

    int tid = threadIdx.x;
    int jg = tid & 7;
    int sg = tid >> 3;
    int tokbase = blockIdx.x * 64;
    int split = blockIdx.y;
    int b = tokbase >> 11;
    int k0base = split * HSPLIT;

    unsigned long long acc[8];
#pragma unroll
    for (int i = 0; i < 8; i++) acc[i] = 0ULL;

    const float* xb = x + (size_t)tokbase * Hh + k0base;
    const float4* acb = (const float4*)(g_Acd + ((size_t)b * Hh + k0base) * Jj);

    float4 px[4], pa[4];

    // prefetch chunk 0
#pragma unroll
    for (int i = 0; i < 4; i++) {
        int f4 = tid + 128 * i;
        int tok = f4 >> 3, kq = f4 & 7;
        px[i] = *(const float4*)&xb[(size_t)tok * Hh + kq * 4];
        pa[i] = acb[tid + 128 * i];
    }

    for (int g = 0; g < NCHUNK; g++) {
        __syncthreads();
        // store prefetched regs -> smem
#pragma unroll
        for (int i = 0; i < 4; i++) {
            int f4 = tid + 128 * i;
            int tok = f4 >> 3, kq = f4 & 7;
            xs[kq * 4 + 0][tok] = px[i].x;
            xs[kq * 4 + 1][tok] = px[i].y;
            xs[kq * 4 + 2][tok] = px[i].z;
            xs[kq * 4 + 3][tok] = px[i].w;
            ((float4*)as_d)[tid + 128 * i] = pa[i];
        }
        __syncthreads();
        // issue next chunk's loads (consumed after compute -> hidden)
        if (g + 1 < NCHUNK) {
            int k0 = (g + 1) * KC;
#pragma unroll
            for (int i = 0; i < 4; i++) {
                int f4 = tid + 128 * i;
                int tok = f4 >> 3, kq = f4 & 7;
                px[i] = *(const float4*)&xb[(size_t)tok * Hh + k0 + kq * 4];
                // one k-row of Acd = 32 float2 = 16 float4 -> offset k0*16
                pa[i] = acb[(size_t)k0 * 16 + tid + 128 * i];
            }
        }
#pragma unroll
        for (int kk = 0; kk < KC; kk++) {
            ulonglong2 xv  = *(ulonglong2*)&xs[kk][sg * 4];
            ulonglong2 a01 = *(ulonglong2*)&as_d[kk][jg * 4];
            ulonglong2 a23 = *(ulonglong2*)&as_d[kk][jg * 4 + 2];
            acc[0] = fma2(xv.x, a01.x, acc[0]);
            acc[1] = fma2(xv.y, a01.x, acc[1]);
            acc[2] = fma2(xv.x, a01.y, acc[2]);
            acc[3] = fma2(xv.y, a01.y, acc[3]);
            acc[4] = fma2(xv.x, a23.x, acc[4]);
            acc[5] = fma2(xv.y, a23.x, acc[5]);
            acc[6] = fma2(xv.x, a23.y, acc[6]);
            acc[7] = fma2(xv.y, a23.y, acc[7]);
        }
    }

    float* lp = g_lowp + (size_t)split * NTOK * Jj;
#pragma unroll
    for (int c = 0; c < 4; c++) {
#pragma unroll
        for (int tp = 0; tp < 2; tp++) {
            U2 u; u.u = acc[c * 2 + tp];
            int j = jg * 4 + c;
            int t0 = tokbase + sg * 4 + tp * 2;
            lp[(size_t)t0 * Jj + j]       = u.f.x;
            lp[(size_t)(t0 + 1) * Jj + j] = u.f.y;
        }
    }
}

// ---------------------------------------------------------------------------
// reduce: sum the NSPLIT partials, write duplicated f32x2 low.
// grid 256, 256 threads, 8 elems/thread.
// ---------------------------------------------------------------------------
__global__ void __launch_bounds__(256) reduce_kernel()
{
    int base = blockIdx.x * 2048;
#pragma unroll
    for (int r = 0; r < 8; r++) {
        int i = base + r * 256 + threadIdx.x;
        float v = g_lowp[i]
                + g_lowp[(size_t)NTOK * Jj + i]
                + g_lowp[(size_t)2 * NTOK * Jj + i]
                + g_lowp[(size_t)3 * NTOK * Jj + i];
        g_lowdup[i] = make_float2(v, v);
    }
}

// ---------------------------------------------------------------------------
// out: out[tok][h] = base[tok][h] + sum_j low[tok][j] * Bc[b][j][h]
// grid (256 token-tiles of 64, 14 h-tiles of 256), 128 threads.
// ---------------------------------------------------------------------------
#define HT 256
#define TT 64

__global__ void __launch_bounds__(128) out_kernel(const float* __restrict__ base,
                                                  float* __restrict__ out)
{
    __shared__ __align__(16) float  sB[Jj][HT];       // 32 KB
    __shared__ __align__(16) float2 sLow[Jj][TT + 4]; // [j][tok] dup; row 68*8B (16B-aligned)

    int tid = threadIdx.x;
    int h0 = blockIdx.y * HT;
    int tok0 = blockIdx.x * TT;
    int b = tok0 >> 11;

    const float* bc = g_Bc + (size_t)b * Jj * Hh + h0;
#pragma unroll
    for (int i = 0; i < 16; i++) {
        int f4 = tid + 128 * i;
        int j = f4 >> 6;
        int hq = f4 & 63;
        *(float4*)&sB[j][hq * 4] = *(const float4*)&bc[(size_t)j * Hh + hq * 4];
    }
#pragma unroll
    for (int i = 0; i < 16; i++) {
        int iv = tid + 128 * i;
        int j = iv & 31;
        int t = iv >> 5;
        sLow[j][t] = g_lowdup[(size_t)(tok0 + t) * Jj + j];
    }
    __syncthreads();

    int g = tid >> 6;        // token half (32 tokens each)
    int hq = tid & 63;

#pragma unroll 1
    for (int p = 0; p < 4; p++) {
        int tl = g * 32 + p * 8;
        unsigned long long acc[8][2];
#pragma unroll
        for (int t = 0; t < 8; t++) { acc[t][0] = 0ULL; acc[t][1] = 0ULL; }

#pragma unroll 8
        for (int j = 0; j < Jj; j++) {
            ulonglong2 bv = *(ulonglong2*)&sB[j][hq * 4];
            ulonglong2 l0 = *(ulonglong2*)&sLow[j][tl];
            ulonglong2 l1 = *(ulonglong2*)&sLow[j][tl + 2];
            ulonglong2 l2 = *(ulonglong2*)&sLow[j][tl + 4];
            ulonglong2 l3 = *(ulonglong2*)&sLow[j][tl + 6];
            acc[0][0] = fma2(bv.x, l0.x, acc[0][0]); acc[0][1] = fma2(bv.y, l0.x, acc[0][1]);
            acc[1][0] = fma2(bv.x, l0.y, acc[1][0]); acc[1][1] = fma2(bv.y, l0.y, acc[1][1]);
            acc[2][0] = fma2(bv.x, l1.x, acc[2][0]); acc[2][1] = fma2(bv.y, l1.x, acc[2][1]);
            acc[3][0] = fma2(bv.x, l1.y, acc[3][0]); acc[3][1] = fma2(bv.y, l1.y, acc[3][1]);
            acc[4][0] = fma2(bv.x, l2.x, acc[4][0]); acc[4][1] = fma2(bv.y, l2.x, acc[4][1]);
            acc[5][0] = fma2(bv.x, l2.y, acc[5][0]); acc[5][1] = fma2(bv.y, l2.y, acc[5][1]);
            acc[6][0] = fma2(bv.x, l3.x, acc[6][0]); acc[6][1] = fma2(bv.y, l3.x, acc[6][1]);
            acc[7][0] = fma2(bv.x, l3.y, acc[7][0]); acc[7][1] = fma2(bv.y, l3.y, acc[7][1]);
        }

#pragma unroll
        for (int t = 0; t < 8; t++) {
            size_t gi = (size_t)(tok0 + tl + t) * Hh + h0 + hq * 4;
            float4 bs = *(const float4*)&base[gi];
            U2 a0, a1; a0.u = acc[t][0]; a1.u = acc[t][1];
            float4 o = make_float4(bs.x + a0.f.x, bs.y + a0.f.y,
                                   bs.z + a1.f.x, bs.w + a1.f.y);
            *(float4*)&out[gi] = o;
        }
    }
}

// ---------------------------------------------------------------------------
extern "C" void kernel_launch(void* const* d_in, const int* in_sizes, int n_in,
                              void* d_out, int out_size)
{
    const float* x    = (const float*)d_in[0];
    const float* base = (const float*)d_in[1];
    const float* lA   = (const float*)d_in[2];
    const float* lB   = (const float*)d_in[3];
    const float* w    = (const float*)d_in[4];
    const int*   idx  = (const int*)  d_in[5];
    float* out = (float*)d_out;

    prep_kernel<<<dim3(Bb, Hh / 256), 256>>>(lA, lB, w, idx);
    low_kernel<<<dim3(NTOK / 64, NSPLIT), 128>>>(x);
    reduce_kernel<<<256, 256>>>();
    out_kernel<<<dim3(NTOK / TT, Hh / HT), 128>>>(base, out);
}

// round 6
// speedup vs baseline: 2.7169x; 1.9338x over previous
#include <cuda_runtime.h>
#include <cuda_bf16.h>
#include <cstdint>

#define Bb 8
#define Ss 2048
#define Hh 3584
#define Ee 8
#define Rr 16
#define Kk 2
#define Jj 32
#define SCALING 2.0f

#define NSPLIT 4
#define HSPLIT (Hh / NSPLIT)     // 896
#define KC 32
#define NCHUNK (HSPLIT / KC)     // 28
#define NTOK (Bb * Ss)           // 16384

// Scratch (static device globals — no allocation). 16B-aligned (float4 access).
__device__ __align__(16) float g_Ac [(size_t)Bb * Hh * Jj];          // [b][h][j], w*scaling folded
__device__ __align__(16) float g_Bc [(size_t)Bb * Jj * Hh];          // [b][j][h]
__device__ __align__(16) float g_lowp[(size_t)NSPLIT * NTOK * Jj];   // partials [split][tok][j]
__device__ __align__(16) float g_low [(size_t)NTOK * Jj];            // [tok][j]

union U2 { unsigned long long u; float2 f; };

__device__ __forceinline__ unsigned long long fma2(unsigned long long a,
                                                   unsigned long long b,
                                                   unsigned long long c) {
    unsigned long long d;
    asm("fma.rn.f32x2 %0, %1, %2, %3;" : "=l"(d) : "l"(a), "l"(b), "l"(c));
    return d;
}
// duplicate a scalar into both halves of a packed f32x2 operand (register-only)
__device__ __forceinline__ unsigned long long dup2(float v) {
    unsigned long long d;
    asm("mov.b64 %0, {%1, %1};" : "=l"(d) : "f"(v));
    return d;
}

// ---------------------------------------------------------------------------
// prep: Ac [b][h][j] (natural float, j-fast coalesced) and Bc [b][j][h].
// grid (Bb, Hh/256), 256 threads.
// ---------------------------------------------------------------------------
__global__ void __launch_bounds__(256) prep_kernel(const float* __restrict__ A,
                                                   const float* __restrict__ Bm,
                                                   const float* __restrict__ w,
                                                   const int*   __restrict__ idx)
{
    __shared__ int   es[Jj];
    __shared__ float scs[Jj];
    int b = blockIdx.x;
    int hb = blockIdx.y * 256;
    int tid = threadIdx.x;
    if (tid < Jj) {
        int k = tid >> 4;
        es[tid]  = idx[b * Kk + k];
        scs[tid] = w[b * Kk + k] * SCALING;
    }
    __syncthreads();

    for (int t = tid; t < 256 * Jj; t += 256) {
        int h = hb + (t >> 5);
        int j = t & 31;
        int r = j & 15;
        g_Ac[((size_t)b * Hh + h) * Jj + j] =
            A[((size_t)(es[j] * Rr + r)) * Hh + h] * scs[j];
    }
    for (int t = tid; t < 256 * Jj; t += 256) {
        int j = t >> 8;
        int h = hb + (t & 255);
        int r = j & 15;
        g_Bc[((size_t)b * Jj + j) * Hh + h] =
            Bm[((size_t)es[j] * Hh + h) * Rr + r];
    }
}

// ---------------------------------------------------------------------------
// low: partial low over a k-split. grid (256 tok-tiles of 64, NSPLIT), 128 thr.
// Thread = 4 tok x 4 j (2 j-pairs).  8 j-groups x 4 j = 32 j; 16 tok-groups
// x 4 tok = 64 tok  -> 128 threads cover the 64x32 tile exactly.
// x natural [tok][k] in smem (no transpose), A natural [k][j] (no dup);
// x scalars duplicated into f32x2 in registers.
// ---------------------------------------------------------------------------
__global__ void __launch_bounds__(128) low_kernel(const float* __restrict__ x)
{
    __shared__ __align__(16) float xsm[64][36];    // [tok][k]; row 144B (16B-aligned)
    __shared__ __align__(16) float asm_[KC][Jj];   // [k][j] natural; row 128B

    int tid = threadIdx.x;
    int jg = tid & 7;          // 8 j-groups of 4 (2 j-pairs)
    int sg = tid >> 3;         // 16 token-groups of 4
    int tokbase = blockIdx.x * 64;
    int split = blockIdx.y;
    int b = tokbase >> 11;
    int k0base = split * HSPLIT;

    unsigned long long acc[4][2];   // [tok c][j-pair q]
#pragma unroll
    for (int c = 0; c < 4; c++) { acc[c][0] = 0ULL; acc[c][1] = 0ULL; }

    const float* xb = x + (size_t)tokbase * Hh + k0base;
    const float4* acb = (const float4*)(g_Ac + ((size_t)b * Hh + k0base) * Jj);

    float4 px[4], pa[2];

    // prefetch chunk 0
#pragma unroll
    for (int i = 0; i < 4; i++) {
        int f4 = tid + 128 * i;
        int tok = f4 >> 3, kq = f4 & 7;
        px[i] = *(const float4*)&xb[(size_t)tok * Hh + kq * 4];
    }
#pragma unroll
    for (int i = 0; i < 2; i++) pa[i] = acb[tid + 128 * i];

    for (int g = 0; g < NCHUNK; g++) {
        __syncthreads();
#pragma unroll
        for (int i = 0; i < 4; i++) {
            int f4 = tid + 128 * i;
            int tok = f4 >> 3, kq = f4 & 7;
            *(float4*)&xsm[tok][kq * 4] = px[i];
        }
#pragma unroll
        for (int i = 0; i < 2; i++)
            ((float4*)asm_)[tid + 128 * i] = pa[i];
        __syncthreads();

        if (g + 1 < NCHUNK) {
            int k0 = (g + 1) * KC;
#pragma unroll
            for (int i = 0; i < 4; i++) {
                int f4 = tid + 128 * i;
                int tok = f4 >> 3, kq = f4 & 7;
                px[i] = *(const float4*)&xb[(size_t)tok * Hh + k0 + kq * 4];
            }
#pragma unroll
            for (int i = 0; i < 2; i++)
                pa[i] = acb[(size_t)k0 * 8 + tid + 128 * i];  // 8 float4 per k-row
        }

#pragma unroll 2
        for (int kk4 = 0; kk4 < KC / 4; kk4++) {
            float4 xq[4];
#pragma unroll
            for (int c = 0; c < 4; c++)
                xq[c] = *(const float4*)&xsm[sg * 4 + c][kk4 * 4];
#pragma unroll
            for (int kl = 0; kl < 4; kl++) {
                int kk = kk4 * 4 + kl;
                // 4 j values = 2 f32x2 pairs; jg*4 floats = 16B aligned
                ulonglong2 av = *(const ulonglong2*)&asm_[kk][jg * 4];
#pragma unroll
                for (int c = 0; c < 4; c++) {
                    float xv = (kl == 0) ? xq[c].x : (kl == 1) ? xq[c].y
                             : (kl == 2) ? xq[c].z : xq[c].w;
                    unsigned long long xd = dup2(xv);
                    acc[c][0] = fma2(xd, av.x, acc[c][0]);
                    acc[c][1] = fma2(xd, av.y, acc[c][1]);
                }
            }
        }
    }

    float* lp = g_lowp + (size_t)split * NTOK * Jj;
#pragma unroll
    for (int c = 0; c < 4; c++) {
        int tok = tokbase + sg * 4 + c;
#pragma unroll
        for (int q = 0; q < 2; q++) {
            U2 u; u.u = acc[c][q];
            *(float2*)&lp[(size_t)tok * Jj + jg * 4 + q * 2] = u.f;
        }
    }
}

// ---------------------------------------------------------------------------
// reduce: sum the NSPLIT partials (natural float output).
// grid 256, 256 threads, 8 elems/thread.
// ---------------------------------------------------------------------------
__global__ void __launch_bounds__(256) reduce_kernel()
{
    int base = blockIdx.x * 2048;
#pragma unroll
    for (int r = 0; r < 8; r++) {
        int i = base + r * 256 + threadIdx.x;
        g_low[i] = g_lowp[i]
                 + g_lowp[(size_t)NTOK * Jj + i]
                 + g_lowp[(size_t)2 * NTOK * Jj + i]
                 + g_lowp[(size_t)3 * NTOK * Jj + i];
    }
}

// ---------------------------------------------------------------------------
// out: out[tok][h] = base[tok][h] + sum_j low[tok][j] * Bc[b][j][h]
// grid (256 token-tiles of 64, 14 h-tiles of 256), 128 threads.
// Thread = 4 h (2 f32x2) x 16 tokens per pass, 2 passes. low natural in smem,
// dup'd in registers.
// ---------------------------------------------------------------------------
#define HT 256
#define TT 64

__global__ void __launch_bounds__(128) out_kernel(const float* __restrict__ base,
                                                  float* __restrict__ out)
{
    __shared__ __align__(16) float sB[Jj][HT];        // 32 KB
    __shared__ __align__(16) float sLowF[Jj][68];     // [j][tok] natural; row 272B

    int tid = threadIdx.x;
    int h0 = blockIdx.y * HT;
    int tok0 = blockIdx.x * TT;
    int b = tok0 >> 11;

    const float* bc = g_Bc + (size_t)b * Jj * Hh + h0;
#pragma unroll
    for (int i = 0; i < 16; i++) {
        int f4 = tid + 128 * i;
        int j = f4 >> 6;
        int hq = f4 & 63;
        *(float4*)&sB[j][hq * 4] = *(const float4*)&bc[(size_t)j * Hh + hq * 4];
    }
    // low tile: coalesced LDG (j fast), STS.128 into [j][tok] rows
#pragma unroll
    for (int i = 0; i < 4; i++) {
        int iv = tid + 128 * i;
        int j = iv & 31;
        int tg = iv >> 5;               // 16 groups of 4 tokens
        float4 v;
        v.x = g_low[(size_t)(tok0 + tg * 4 + 0) * Jj + j];
        v.y = g_low[(size_t)(tok0 + tg * 4 + 1) * Jj + j];
        v.z = g_low[(size_t)(tok0 + tg * 4 + 2) * Jj + j];
        v.w = g_low[(size_t)(tok0 + tg * 4 + 3) * Jj + j];
        *(float4*)&sLowF[j][tg * 4] = v;
    }
    __syncthreads();

    int g = tid >> 6;        // token half (32 tokens each)
    int hq = tid & 63;       // h offset = hq*4

#pragma unroll 1
    for (int p = 0; p < 2; p++) {
        int tl = g * 32 + p * 16;        // 16 tokens this pass
        unsigned long long acc[16][2];
#pragma unroll
        for (int t = 0; t < 16; t++) { acc[t][0] = 0ULL; acc[t][1] = 0ULL; }

#pragma unroll 4
        for (int j = 0; j < Jj; j++) {
            ulonglong2 bv = *(const ulonglong2*)&sB[j][hq * 4];
#pragma unroll
            for (int q = 0; q < 4; q++) {
                float4 lf = *(const float4*)&sLowF[j][tl + q * 4];
                unsigned long long d0 = dup2(lf.x), d1 = dup2(lf.y),
                                   d2 = dup2(lf.z), d3 = dup2(lf.w);
                acc[q*4+0][0] = fma2(bv.x, d0, acc[q*4+0][0]);
                acc[q*4+0][1] = fma2(bv.y, d0, acc[q*4+0][1]);
                acc[q*4+1][0] = fma2(bv.x, d1, acc[q*4+1][0]);
                acc[q*4+1][1] = fma2(bv.y, d1, acc[q*4+1][1]);
                acc[q*4+2][0] = fma2(bv.x, d2, acc[q*4+2][0]);
                acc[q*4+2][1] = fma2(bv.y, d2, acc[q*4+2][1]);
                acc[q*4+3][0] = fma2(bv.x, d3, acc[q*4+3][0]);
                acc[q*4+3][1] = fma2(bv.y, d3, acc[q*4+3][1]);
            }
        }

#pragma unroll
        for (int t = 0; t < 16; t++) {
            size_t gi = (size_t)(tok0 + tl + t) * Hh + h0 + hq * 4;
            float4 bs = *(const float4*)&base[gi];
            U2 a0, a1; a0.u = acc[t][0]; a1.u = acc[t][1];
            float4 o = make_float4(bs.x + a0.f.x, bs.y + a0.f.y,
                                   bs.z + a1.f.x, bs.w + a1.f.y);
            *(float4*)&out[gi] = o;
        }
    }
}

// ---------------------------------------------------------------------------
extern "C" void kernel_launch(void* const* d_in, const int* in_sizes, int n_in,
                              void* d_out, int out_size)
{
    const float* x    = (const float*)d_in[0];
    const float* base = (const float*)d_in[1];
    const float* lA   = (const float*)d_in[2];
    const float* lB   = (const float*)d_in[3];
    const float* w    = (const float*)d_in[4];
    const int*   idx  = (const int*)  d_in[5];
    float* out = (float*)d_out;

    prep_kernel<<<dim3(Bb, Hh / 256), 256>>>(lA, lB, w, idx);
    low_kernel<<<dim3(NTOK / 64, NSPLIT), 128>>>(x);
    reduce_kernel<<<256, 256>>>();
    out_kernel<<<dim3(NTOK / TT, Hh / HT), 128>>>(base, out);
}